// round 9
// baseline (speedup 1.0000x reference)
#include <cuda_runtime.h>
#include <cuda_fp16.h>
#include <cstdint>
#include <cfloat>

#define NPTS 1536
#define TLEN 20
#define HDIM 64
#define EDIM 16
#define MDIM 128
#define IPB  4              // i's per block (one per warp)
#define JC   32             // j rows per chunk
#define NCHUNK 48
#define JSPLIT 6            // j-range splits
#define CPB (NCHUNK / JSPLIT)   // 8
#define NIG (NPTS / IPB)    // 384 i-groups
#define THREADS 128

// scratch (__device__ globals: allocation-free rule). Stored k-PERMUTED (perm32).
__device__ __half g_Ah[NPTS * MDIM];
__device__ __half g_Bh[NPTS * MDIM];
__device__ __half g_W2h[HDIM * MDIM];   // W2^T, h-major, permuted fp16

// perm32: within each 32-k group, pack fragment halves so ONE 16B load carries
// the mma A/B fragment pairs for TWO consecutive k16 steps:
//   lane quad fc reads halves [fc*8 .. fc*8+7] =
//   [a0(even ks): m=2fc,2fc+1][a2(even): 8+2fc,+1][a0(odd): 16+2fc][a2(odd): 24+2fc]
__host__ __device__ __forceinline__ int perm32(int m) {
    int g = m >> 5, r = m & 31;
    int st = (r >> 4) & 1, w = r & 15;
    int fc = (w & 7) >> 1;
    int within = ((w < 8) ? 0 : 2) + (w & 1);
    return g * 32 + fc * 8 + st * 4 + within;
}

// ---------------------------------------------------------------------------
// Precompute: A[j,m], B[j,m] (fp16, perm32) + W2^T fp16 perm32 + zero out
// grid = NPTS, 128 threads (one per m)
// ---------------------------------------------------------------------------
__global__ void prep_kernel(const float* __restrict__ hidden,
                            const float* __restrict__ gt,
                            const float* __restrict__ We,
                            const float* __restrict__ be,
                            const float* __restrict__ W1,
                            const float* __restrict__ b1,
                            const float* __restrict__ W2,
                            float* __restrict__ out) {
    int j = blockIdx.x;
    int m = threadIdx.x;               // 0..127
    __shared__ float hs[HDIM];
    __shared__ float ev[2];
    if (m < HDIM) hs[m] = hidden[j * HDIM + m];
    if (m < 2)    ev[m] = gt[(j * TLEN + (TLEN - 1)) * 2 + m];
    __syncthreads();

    float p0 = 0.f, p1 = 0.f, q = 0.f;
#pragma unroll
    for (int e = 0; e < EDIM; e++) {
        float wv = W1[(HDIM + e) * MDIM + m];
        p0 += We[e] * wv;
        p1 += We[EDIM + e] * wv;
        q  += be[e] * wv;
    }
    float s = 0.f;
#pragma unroll 8
    for (int h = 0; h < HDIM; h++) s += hs[h] * W1[h * MDIM + m];

    float d = ev[0] * p0 + ev[1] * p1;
    int mp = perm32(m);
    g_Bh[j * MDIM + mp] = __float2half(d);
    g_Ah[j * MDIM + mp] = __float2half(s + d + q + b1[m]);

    if (m < HDIM) out[j * HDIM + m] = 0.f;                 // zero output (atomicMax base)
    if (j < HDIM) g_W2h[j * MDIM + mp] = __float2half(W2[m * HDIM + j]);
}

// ---------------------------------------------------------------------------
// Main: grid = NIG*JSPLIT = 2304 blocks, 128 threads (4 warps, warp w -> i).
// NO shared memory, NO barriers: all fragments via LDG.128 (L1-resident),
// one uint4 per TWO k16 mma steps thanks to perm32.
// ig varies fastest across blockIdx so co-resident blocks share A in L1.
// ---------------------------------------------------------------------------
__global__ void __launch_bounds__(THREADS, 4)
main_kernel(const float* __restrict__ b2, float* __restrict__ out) {
    const int tid  = threadIdx.x;
    const int w    = tid >> 5;
    const int lane = tid & 31;
    const int ig   = blockIdx.x % NIG;       // fastest: L1 sharing of A chunks
    const int js   = blockIdx.x / NIG;
    const int i    = ig * IPB + w;
    const int jc0  = js * CPB;

    const int fr = lane >> 2;          // fragment row (0..7)
    const int fc = lane & 3;           // fragment k-quad (0..3)
    const int koff = fc * 8;           // halves within 32-k group

    // ---- B[i] fragments: 4 uint4 = 16 regs, one LDG.128 per 32-k group ----
    uint4 bf[4];
#pragma unroll
    for (int g2 = 0; g2 < 4; g2++)
        bf[g2] = *(const uint4*)&g_Bh[i * MDIM + g2 * 32 + koff];

    float mx[8][2];
#pragma unroll
    for (int t = 0; t < 8; t++) { mx[t][0] = -FLT_MAX; mx[t][1] = -FLT_MAX; }

    const __half2 zero2 = __float2half2_rn(0.f);

    for (int c = 0; c < CPB; c++) {
        const __half* Ab = g_Ah + (jc0 + c) * JC * MDIM;

        float acc[2][8][4];
#pragma unroll
        for (int jt = 0; jt < 2; jt++)
#pragma unroll
            for (int ht = 0; ht < 8; ht++)
#pragma unroll
                for (int r = 0; r < 4; r++) acc[jt][ht][r] = 0.f;

#pragma unroll
        for (int g2 = 0; g2 < 4; g2++) {
            const int kbase = g2 * 32 + koff;
            const __half2 bx = *(const __half2*)&bf[g2].x;   // even a0 subtrahend
            const __half2 by = *(const __half2*)&bf[g2].y;   // even a2
            const __half2 bz = *(const __half2*)&bf[g2].z;   // odd a0
            const __half2 bw = *(const __half2*)&bf[g2].w;   // odd a2

            uint32_t ze[2][4], zo[2][4];
#pragma unroll
            for (int jt = 0; jt < 2; jt++) {
                uint4 v0 = *(const uint4*)&Ab[(jt * 16 + fr) * MDIM + kbase];      // rows 0-7
                uint4 v1 = *(const uint4*)&Ab[(jt * 16 + 8 + fr) * MDIM + kbase];  // rows 8-15
                __half2 a0e = __hmax2(__hsub2(*(__half2*)&v0.x, bx), zero2);
                __half2 a2e = __hmax2(__hsub2(*(__half2*)&v0.y, by), zero2);
                __half2 a0o = __hmax2(__hsub2(*(__half2*)&v0.z, bz), zero2);
                __half2 a2o = __hmax2(__hsub2(*(__half2*)&v0.w, bw), zero2);
                __half2 a1e = __hmax2(__hsub2(*(__half2*)&v1.x, bx), zero2);
                __half2 a3e = __hmax2(__hsub2(*(__half2*)&v1.y, by), zero2);
                __half2 a1o = __hmax2(__hsub2(*(__half2*)&v1.z, bz), zero2);
                __half2 a3o = __hmax2(__hsub2(*(__half2*)&v1.w, bw), zero2);
                ze[jt][0] = *(uint32_t*)&a0e; ze[jt][1] = *(uint32_t*)&a1e;
                ze[jt][2] = *(uint32_t*)&a2e; ze[jt][3] = *(uint32_t*)&a3e;
                zo[jt][0] = *(uint32_t*)&a0o; zo[jt][1] = *(uint32_t*)&a1o;
                zo[jt][2] = *(uint32_t*)&a2o; zo[jt][3] = *(uint32_t*)&a3o;
            }
#pragma unroll
            for (int ht = 0; ht < 8; ht++) {
                uint4 wv = *(const uint4*)&g_W2h[(ht * 8 + fr) * MDIM + kbase];
                // wv = {b0_even, b1_even, b0_odd, b1_odd}
#pragma unroll
                for (int jt = 0; jt < 2; jt++) {
                    asm volatile(
                        "mma.sync.aligned.m16n8k16.row.col.f32.f16.f16.f32 "
                        "{%0,%1,%2,%3},{%4,%5,%6,%7},{%8,%9},{%0,%1,%2,%3};"
                        : "+f"(acc[jt][ht][0]), "+f"(acc[jt][ht][1]),
                          "+f"(acc[jt][ht][2]), "+f"(acc[jt][ht][3])
                        : "r"(ze[jt][0]), "r"(ze[jt][1]), "r"(ze[jt][2]), "r"(ze[jt][3]),
                          "r"(wv.x), "r"(wv.y));
                    asm volatile(
                        "mma.sync.aligned.m16n8k16.row.col.f32.f16.f16.f32 "
                        "{%0,%1,%2,%3},{%4,%5,%6,%7},{%8,%9},{%0,%1,%2,%3};"
                        : "+f"(acc[jt][ht][0]), "+f"(acc[jt][ht][1]),
                          "+f"(acc[jt][ht][2]), "+f"(acc[jt][ht][3])
                        : "r"(zo[jt][0]), "r"(zo[jt][1]), "r"(zo[jt][2]), "r"(zo[jt][3]),
                          "r"(wv.z), "r"(wv.w));
                }
            }
        }
        // fold both j-tiles into running max
#pragma unroll
        for (int jt = 0; jt < 2; jt++)
#pragma unroll
            for (int ht = 0; ht < 8; ht++) {
                mx[ht][0] = fmaxf(mx[ht][0], fmaxf(acc[jt][ht][0], acc[jt][ht][2]));
                mx[ht][1] = fmaxf(mx[ht][1], fmaxf(acc[jt][ht][1], acc[jt][ht][3]));
            }
    }

    // ---- reduce max across j-row lanes (same h: lane%4 groups) ----
#pragma unroll
    for (int ht = 0; ht < 8; ht++) {
#pragma unroll
        for (int s = 4; s < 32; s <<= 1) {
            mx[ht][0] = fmaxf(mx[ht][0], __shfl_xor_sync(0xffffffffu, mx[ht][0], s));
            mx[ht][1] = fmaxf(mx[ht][1], __shfl_xor_sync(0xffffffffu, mx[ht][1], s));
        }
    }
    if (lane < 4) {
#pragma unroll
        for (int ht = 0; ht < 8; ht++) {
            int h = ht * 8 + 2 * lane;
            float v0 = fmaxf(mx[ht][0] + b2[h], 0.f);
            float v1 = fmaxf(mx[ht][1] + b2[h + 1], 0.f);
            // relu output >= 0: int-ordered atomicMax exact; out pre-zeroed in prep
            atomicMax((int*)&out[i * HDIM + h],     __float_as_int(v0));
            atomicMax((int*)&out[i * HDIM + h + 1], __float_as_int(v1));
        }
    }
}

// ---------------------------------------------------------------------------
extern "C" void kernel_launch(void* const* d_in, const int* in_sizes, int n_in,
                              void* d_out, int out_size) {
    const float* hidden = (const float*)d_in[0];
    const float* gt     = (const float*)d_in[1];
    const float* We     = (const float*)d_in[2];
    const float* be     = (const float*)d_in[3];
    const float* W1     = (const float*)d_in[4];
    const float* b1     = (const float*)d_in[5];
    const float* W2     = (const float*)d_in[6];
    const float* b2     = (const float*)d_in[7];
    float* out = (float*)d_out;

    prep_kernel<<<NPTS, MDIM>>>(hidden, gt, We, be, W1, b1, W2, out);
    main_kernel<<<NIG * JSPLIT, THREADS>>>(b2, out);
}